// round 3
// baseline (speedup 1.0000x reference)
#include <cuda_runtime.h>
#include <math.h>

#define VOCAB 128000
#define EMB   2048
#define HID   4096
#define OUT   128000

// Persistent decoder grid: 6 blocks/SM * 148 SMs, guaranteed co-resident
// via __launch_bounds__(256, 6). (Also fits GB300's 152 SMs.)
#define GRID_DEC 888

// ---- scratch (allocation-free: __device__ globals) ----
__device__ float    g_hnew[HID];
__device__ float    g_logits[OUT];
__device__ float    g_maxpart[GRID_DEC];
__device__ float    g_sumpart[GRID_DEC];
__device__ unsigned g_bar0, g_bar1;

__device__ __forceinline__ float warp_sum(float v) {
    #pragma unroll
    for (int o = 16; o; o >>= 1) v += __shfl_down_sync(0xffffffffu, v, o);
    return v;
}

// Software grid barrier: all GRID_DEC blocks are co-resident by construction.
__device__ __forceinline__ void grid_bar(unsigned* ctr) {
    __syncthreads();
    if (threadIdx.x == 0) {
        __threadfence();                       // release: publish our writes
        atomicAdd(ctr, 1u);
        while (*(volatile unsigned*)ctr < GRID_DEC) __nanosleep(64);
        __threadfence();                       // acquire: see others' writes
    }
    __syncthreads();
}

// ---------------------------------------------------------------------------
// Kernel 1: GRU cell. One block per hidden unit j. Also resets the
// grid-barrier counters for the following persistent kernel (stream order
// guarantees visibility; deterministic across graph replays).
// ---------------------------------------------------------------------------
__global__ void __launch_bounds__(256) gru_cell_kernel(
    const int*   __restrict__ token,
    const float* __restrict__ hidden,
    const float* __restrict__ W_emb,
    const float* __restrict__ W_ih,
    const float* __restrict__ W_hh,
    const float* __restrict__ b_ih,
    const float* __restrict__ b_hh,
    float*       __restrict__ out_h)
{
    const int j   = blockIdx.x;
    const int tid = threadIdx.x;
    const int warp = tid >> 5, lane = tid & 31;

    if (j == 0 && tid == 0) { g_bar0 = 0u; g_bar1 = 0u; }

    const float4* x4  = (const float4*)(W_emb + (size_t)token[0] * EMB);
    const float4* h4  = (const float4*)hidden;
    const float4* wir = (const float4*)(W_ih + (size_t)j           * EMB);
    const float4* wiz = (const float4*)(W_ih + (size_t)(j +   HID) * EMB);
    const float4* win = (const float4*)(W_ih + (size_t)(j + 2*HID) * EMB);
    const float4* whr = (const float4*)(W_hh + (size_t)j           * HID);
    const float4* whz = (const float4*)(W_hh + (size_t)(j +   HID) * HID);
    const float4* whn = (const float4*)(W_hh + (size_t)(j + 2*HID) * HID);

    float s[6] = {0.f, 0.f, 0.f, 0.f, 0.f, 0.f};

    #pragma unroll
    for (int it = 0; it < EMB / 4 / 256; ++it) {        // 2 iters
        int k = tid + it * 256;
        float4 xv = x4[k];
        float4 a = wir[k]; s[0] += a.x*xv.x + a.y*xv.y + a.z*xv.z + a.w*xv.w;
        float4 b = wiz[k]; s[1] += b.x*xv.x + b.y*xv.y + b.z*xv.z + b.w*xv.w;
        float4 c = win[k]; s[2] += c.x*xv.x + c.y*xv.y + c.z*xv.z + c.w*xv.w;
    }
    #pragma unroll
    for (int it = 0; it < HID / 4 / 256; ++it) {        // 4 iters
        int k = tid + it * 256;
        float4 hv = h4[k];
        float4 a = whr[k]; s[3] += a.x*hv.x + a.y*hv.y + a.z*hv.z + a.w*hv.w;
        float4 b = whz[k]; s[4] += b.x*hv.x + b.y*hv.y + b.z*hv.z + b.w*hv.w;
        float4 c = whn[k]; s[5] += c.x*hv.x + c.y*hv.y + c.z*hv.z + c.w*hv.w;
    }

    __shared__ float red[8][6];
    #pragma unroll
    for (int i = 0; i < 6; ++i) {
        s[i] = warp_sum(s[i]);
        if (lane == 0) red[warp][i] = s[i];
    }
    __syncthreads();

    if (tid == 0) {
        float t[6] = {0.f, 0.f, 0.f, 0.f, 0.f, 0.f};
        #pragma unroll
        for (int w = 0; w < 8; ++w)
            #pragma unroll
            for (int i = 0; i < 6; ++i) t[i] += red[w][i];

        float i_r = t[0] + b_ih[j];
        float i_z = t[1] + b_ih[j + HID];
        float i_n = t[2] + b_ih[j + 2*HID];
        float h_r = t[3] + b_hh[j];
        float h_z = t[4] + b_hh[j + HID];
        float h_n = t[5] + b_hh[j + 2*HID];

        float r = 1.f / (1.f + expf(-(i_r + h_r)));
        float z = 1.f / (1.f + expf(-(i_z + h_z)));
        float n = tanhf(i_n + r * h_n);
        float hn = (1.f - z) * n + z * hidden[j];

        g_hnew[j] = hn;
        if (out_h) out_h[j] = hn;
    }
}

// ---------------------------------------------------------------------------
// Kernel 2 (persistent, fused): decoder GEMV + full softmax.
// Phase 1: each warp streams rows of W_dec (grid-stride by GRID_DEC*8),
//          writes logits, tracks block max -> g_maxpart.
//   [grid barrier]
// Phase 2: global max; each thread owns <=1 output element, computes
//          e = exp(logit - max) kept IN REGISTER, block sum -> g_sumpart.
//   [grid barrier]
// Phase 3: global sum; out[i] = e * inv  (single write, no intermediate).
// ---------------------------------------------------------------------------
__global__ void __launch_bounds__(256, 6) dec_softmax_kernel(
    const float* __restrict__ W_dec,
    const float* __restrict__ b_dec,
    float*       __restrict__ out)
{
    __shared__ float4 sh[HID / 4];     // 16 KB: h_new staged once per block
    __shared__ float  sred[256];

    const int tid  = threadIdx.x;
    const int warp = tid >> 5, lane = tid & 31;

    for (int k = tid; k < HID / 4; k += 256)
        sh[k] = ((const float4*)g_hnew)[k];
    __syncthreads();

    // ---- Phase 1: logits + local max ----
    float lmax = -INFINITY;
    for (unsigned row = blockIdx.x * 8u + warp; row < OUT; row += GRID_DEC * 8u) {
        const float4* w = (const float4*)(W_dec + (size_t)row * HID);
        float s = 0.f;
        #pragma unroll 4
        for (int it = 0; it < HID / 4 / 32; ++it) {   // 32 iters
            int k = lane + it * 32;
            float4 wv = w[k];
            float4 hv = sh[k];
            s += wv.x*hv.x + wv.y*hv.y + wv.z*hv.z + wv.w*hv.w;
        }
        s = warp_sum(s);
        if (lane == 0) {
            float l = s + b_dec[row];
            g_logits[row] = l;
            lmax = fmaxf(lmax, l);
        }
    }
    sred[tid] = lmax;                  // only lane 0 carries a real value
    __syncthreads();
    #pragma unroll
    for (int st = 128; st; st >>= 1) {
        if (tid < st) sred[tid] = fmaxf(sred[tid], sred[tid + st]);
        __syncthreads();
    }
    if (tid == 0) g_maxpart[blockIdx.x] = sred[0];

    grid_bar(&g_bar0);

    // ---- Phase 2: global max, then exp in register + block sum ----
    float m = -INFINITY;
    for (int i = tid; i < GRID_DEC; i += 256) m = fmaxf(m, g_maxpart[i]);
    __syncthreads();                   // sred reuse
    sred[tid] = m;
    __syncthreads();
    #pragma unroll
    for (int st = 128; st; st >>= 1) {
        if (tid < st) sred[tid] = fmaxf(sred[tid], sred[tid + st]);
        __syncthreads();
    }
    const float gmax = sred[0];
    __syncthreads();

    const int i = blockIdx.x * 256 + tid;   // <=1 element per thread
    float e = 0.f;
    if (i < OUT) e = expf(g_logits[i] - gmax);

    sred[tid] = e;
    __syncthreads();
    #pragma unroll
    for (int st = 128; st; st >>= 1) {
        if (tid < st) sred[tid] += sred[tid + st];
        __syncthreads();
    }
    if (tid == 0) g_sumpart[blockIdx.x] = sred[0];

    grid_bar(&g_bar1);

    // ---- Phase 3: global sum, single final write ----
    float ps = 0.f;
    for (int k = tid; k < GRID_DEC; k += 256) ps += g_sumpart[k];
    __syncthreads();
    sred[tid] = ps;
    __syncthreads();
    #pragma unroll
    for (int st = 128; st; st >>= 1) {
        if (tid < st) sred[tid] += sred[tid + st];
        __syncthreads();
    }
    const float inv = 1.f / sred[0];

    if (i < OUT) out[i] = e * inv;
}

// ---------------------------------------------------------------------------
// Launch. Input order: token, hidden, W_emb, W_ih, W_hh, b_ih, b_hh,
//                      W_dec, b_dec.  Output: [softmax(OUT), h_new(HID)]
// ---------------------------------------------------------------------------
extern "C" void kernel_launch(void* const* d_in, const int* in_sizes, int n_in,
                              void* d_out, int out_size)
{
    const int*   token  = (const int*)  d_in[0];
    const float* hidden = (const float*)d_in[1];
    const float* W_emb  = (const float*)d_in[2];
    const float* W_ih   = (const float*)d_in[3];
    const float* W_hh   = (const float*)d_in[4];
    const float* b_ih   = (const float*)d_in[5];
    const float* b_hh   = (const float*)d_in[6];
    const float* W_dec  = (const float*)d_in[7];
    const float* b_dec  = (const float*)d_in[8];

    float* out   = (float*)d_out;
    float* out_h = (out_size >= OUT + HID) ? (out + OUT) : nullptr;

    gru_cell_kernel<<<HID, 256>>>(token, hidden, W_emb, W_ih, W_hh,
                                  b_ih, b_hh, out_h);
    dec_softmax_kernel<<<GRID_DEC, 256>>>(W_dec, b_dec, out);
}

// round 4
// speedup vs baseline: 1.0956x; 1.0956x over previous
#include <cuda_runtime.h>
#include <math.h>

#define VOCAB 128000
#define EMB   2048
#define HID   4096
#define OUT   128000

#define DEC_WARPS 8                    // rows per block in decoder GEMV
#define DEC_BLOCKS (OUT / DEC_WARPS)   // 16000

// ---- scratch (allocation-free: __device__ globals) ----
__device__ float    g_hnew[HID];
__device__ float    g_logits[OUT];
__device__ float    g_sumpart[256];
__device__ unsigned g_maxbits;         // monotone-encoded global max
__device__ float    g_inv;

__device__ __forceinline__ float warp_sum(float v) {
    #pragma unroll
    for (int o = 16; o; o >>= 1) v += __shfl_down_sync(0xffffffffu, v, o);
    return v;
}

// Monotone float<->uint encoding (order-preserving for all finite floats).
__device__ __forceinline__ unsigned f2mono(float f) {
    unsigned b = __float_as_uint(f);
    return (b & 0x80000000u) ? ~b : (b | 0x80000000u);
}
__device__ __forceinline__ float mono2f(unsigned k) {
    unsigned b = (k & 0x80000000u) ? (k & 0x7fffffffu) : ~k;
    return __uint_as_float(b);
}

// ---------------------------------------------------------------------------
// Kernel 1: GRU cell. One block per hidden unit j. Block 0 also resets the
// global-max accumulator for the decoder (stream order guarantees it lands
// before logits_kernel runs; deterministic across graph replays).
// ---------------------------------------------------------------------------
__global__ void __launch_bounds__(256) gru_cell_kernel(
    const int*   __restrict__ token,
    const float* __restrict__ hidden,
    const float* __restrict__ W_emb,
    const float* __restrict__ W_ih,
    const float* __restrict__ W_hh,
    const float* __restrict__ b_ih,
    const float* __restrict__ b_hh,
    float*       __restrict__ out_h)
{
    const int j   = blockIdx.x;
    const int tid = threadIdx.x;
    const int warp = tid >> 5, lane = tid & 31;

    if (j == 0 && tid == 0) g_maxbits = 0u;   // encodes -inf

    const float4* x4  = (const float4*)(W_emb + (size_t)token[0] * EMB);
    const float4* h4  = (const float4*)hidden;
    const float4* wir = (const float4*)(W_ih + (size_t)j           * EMB);
    const float4* wiz = (const float4*)(W_ih + (size_t)(j +   HID) * EMB);
    const float4* win = (const float4*)(W_ih + (size_t)(j + 2*HID) * EMB);
    const float4* whr = (const float4*)(W_hh + (size_t)j           * HID);
    const float4* whz = (const float4*)(W_hh + (size_t)(j +   HID) * HID);
    const float4* whn = (const float4*)(W_hh + (size_t)(j + 2*HID) * HID);

    float s[6] = {0.f, 0.f, 0.f, 0.f, 0.f, 0.f};

    #pragma unroll
    for (int it = 0; it < EMB / 4 / 256; ++it) {        // 2 iters
        int k = tid + it * 256;
        float4 xv = x4[k];                               // L2-resident (reused)
        float4 a = __ldcs(wir + k); s[0] += a.x*xv.x + a.y*xv.y + a.z*xv.z + a.w*xv.w;
        float4 b = __ldcs(wiz + k); s[1] += b.x*xv.x + b.y*xv.y + b.z*xv.z + b.w*xv.w;
        float4 c = __ldcs(win + k); s[2] += c.x*xv.x + c.y*xv.y + c.z*xv.z + c.w*xv.w;
    }
    #pragma unroll
    for (int it = 0; it < HID / 4 / 256; ++it) {        // 4 iters
        int k = tid + it * 256;
        float4 hv = h4[k];                               // L2-resident (reused)
        float4 a = __ldcs(whr + k); s[3] += a.x*hv.x + a.y*hv.y + a.z*hv.z + a.w*hv.w;
        float4 b = __ldcs(whz + k); s[4] += b.x*hv.x + b.y*hv.y + b.z*hv.z + b.w*hv.w;
        float4 c = __ldcs(whn + k); s[5] += c.x*hv.x + c.y*hv.y + c.z*hv.z + c.w*hv.w;
    }

    __shared__ float red[8][6];
    #pragma unroll
    for (int i = 0; i < 6; ++i) {
        s[i] = warp_sum(s[i]);
        if (lane == 0) red[warp][i] = s[i];
    }
    __syncthreads();

    if (tid == 0) {
        float t[6] = {0.f, 0.f, 0.f, 0.f, 0.f, 0.f};
        #pragma unroll
        for (int w = 0; w < 8; ++w)
            #pragma unroll
            for (int i = 0; i < 6; ++i) t[i] += red[w][i];

        float i_r = t[0] + b_ih[j];
        float i_z = t[1] + b_ih[j + HID];
        float i_n = t[2] + b_ih[j + 2*HID];
        float h_r = t[3] + b_hh[j];
        float h_z = t[4] + b_hh[j + HID];
        float h_n = t[5] + b_hh[j + 2*HID];

        float r = 1.f / (1.f + expf(-(i_r + h_r)));
        float z = 1.f / (1.f + expf(-(i_z + h_z)));
        float n = tanhf(i_n + r * h_n);
        float hn = (1.f - z) * n + z * hidden[j];

        g_hnew[j] = hn;
        if (out_h) out_h[j] = hn;
    }
}

// ---------------------------------------------------------------------------
// Kernel 2: decoder GEMV. One row per warp (8 rows/block, 16000 blocks).
// h_new staged once per block in shared. Writes logits; block max published
// via order-independent atomicMax on monotone-encoded bits.
// ---------------------------------------------------------------------------
__global__ void __launch_bounds__(256) logits_kernel(
    const float* __restrict__ W_dec,
    const float* __restrict__ b_dec)
{
    __shared__ float4 sh[HID / 4];     // 16 KB
    __shared__ float  smax[DEC_WARPS];

    const int tid = threadIdx.x;
    for (int k = tid; k < HID / 4; k += 256)
        sh[k] = ((const float4*)g_hnew)[k];
    __syncthreads();

    const int warp = tid >> 5, lane = tid & 31;
    const size_t row = (size_t)blockIdx.x * DEC_WARPS + warp;
    const float4* w = (const float4*)(W_dec + row * HID);

    float s = 0.f;
    #pragma unroll 8
    for (int it = 0; it < HID / 4 / 32; ++it) {   // 32 iters
        int k = lane + it * 32;
        float4 wv = __ldcs(w + k);                 // one-touch: evict-first
        float4 hv = sh[k];
        s += wv.x*hv.x + wv.y*hv.y + wv.z*hv.z + wv.w*hv.w;
    }
    s = warp_sum(s);
    if (lane == 0) {
        float logit = s + b_dec[row];
        g_logits[row] = logit;
        smax[warp] = logit;
    }
    __syncthreads();
    if (tid == 0) {
        float m = smax[0];
        #pragma unroll
        for (int i = 1; i < DEC_WARPS; ++i) m = fmaxf(m, smax[i]);
        atomicMax(&g_maxbits, f2mono(m));          // order-independent
    }
}

// ---------------------------------------------------------------------------
// Kernel 3: exp(logit - max) -> out, per-block partial sums.
// ---------------------------------------------------------------------------
__global__ void __launch_bounds__(256) expsum_kernel(float* __restrict__ out)
{
    const int tid = threadIdx.x;
    const float m = mono2f(g_maxbits);
    float sum = 0.f;
    for (int i = blockIdx.x * 256 + tid; i < OUT; i += 256 * 256) {
        float e = expf(g_logits[i] - m);
        out[i] = e;
        sum += e;
    }
    __shared__ float sm[256];
    sm[tid] = sum; __syncthreads();
    #pragma unroll
    for (int s = 128; s; s >>= 1) {
        if (tid < s) sm[tid] += sm[tid + s];
        __syncthreads();
    }
    if (tid == 0) g_sumpart[blockIdx.x] = sm[0];
}

// ---------------------------------------------------------------------------
// Kernel 4: sum reduce -> 1/sum (single block).
// ---------------------------------------------------------------------------
__global__ void __launch_bounds__(256) sumreduce_kernel()
{
    __shared__ float sm[256];
    const int tid = threadIdx.x;
    sm[tid] = g_sumpart[tid];
    __syncthreads();
    #pragma unroll
    for (int s = 128; s; s >>= 1) {
        if (tid < s) sm[tid] += sm[tid + s];
        __syncthreads();
    }
    if (tid == 0) g_inv = 1.f / sm[0];
}

// ---------------------------------------------------------------------------
// Kernel 5: final scale (reads the already-written exp values in out).
// ---------------------------------------------------------------------------
__global__ void __launch_bounds__(256) scale_kernel(float* __restrict__ out)
{
    const float inv = g_inv;
    const int i = blockIdx.x * 256 + threadIdx.x;
    if (i < OUT) out[i] *= inv;
}

// ---------------------------------------------------------------------------
// Launch. Input order: token, hidden, W_emb, W_ih, W_hh, b_ih, b_hh,
//                      W_dec, b_dec.  Output: [softmax(OUT), h_new(HID)]
// ---------------------------------------------------------------------------
extern "C" void kernel_launch(void* const* d_in, const int* in_sizes, int n_in,
                              void* d_out, int out_size)
{
    const int*   token  = (const int*)  d_in[0];
    const float* hidden = (const float*)d_in[1];
    const float* W_emb  = (const float*)d_in[2];
    const float* W_ih   = (const float*)d_in[3];
    const float* W_hh   = (const float*)d_in[4];
    const float* b_ih   = (const float*)d_in[5];
    const float* b_hh   = (const float*)d_in[6];
    const float* W_dec  = (const float*)d_in[7];
    const float* b_dec  = (const float*)d_in[8];

    float* out   = (float*)d_out;
    float* out_h = (out_size >= OUT + HID) ? (out + OUT) : nullptr;

    gru_cell_kernel<<<HID, 256>>>(token, hidden, W_emb, W_ih, W_hh,
                                  b_ih, b_hh, out_h);
    logits_kernel<<<DEC_BLOCKS, 256>>>(W_dec, b_dec);
    expsum_kernel<<<256, 256>>>(out);
    sumreduce_kernel<<<1, 256>>>();
    scale_kernel<<<(OUT + 255) / 256, 256>>>(out);
}